// round 10
// baseline (speedup 1.0000x reference)
// HNNLayer — factored K=256-concat GEMM + vector-RED implementation (R10; fixes non-ASCII identifier)
#include <cuda_runtime.h>
#include <cstddef>

#define D 128
#define MAXN 50000
#define MAXE 10000

// ---------------- scratch (static device globals; no allocation) ----------------
__device__ __align__(16) float g_S1[MAXE * D];    // sum invDV[s]*vfeat[s] per edge
__device__ __align__(16) float g_S2[MAXE * D];    // sum vout[s] per edge
__device__ __align__(16) float g_VF[MAXN * D];    // _vfeat
__device__ __align__(16) float g_VF2[MAXN * D];   // _vfeat2 (pre-spmm)
__device__ __align__(16) float g_VF2B[MAXN * D];  // vmat spmm result
__device__ __align__(16) float g_c1[MAXE];        // sum invDV[s] per edge
__device__ __align__(16) float g_deg[MAXE];       // incidence count per edge
__device__ __align__(16) float g_Apre[MAXE * D];  // pre-emat-spmm edge feats
__device__ __align__(16) float g_EF[MAXE * D];    // _efeat
__device__ __align__(16) float g_EF2[MAXE * D];   // _efeat2

static inline int divup(int a, int b) { return (a + b - 1) / b; }

// Vector fp32 reduction (sm_90+, PTX ISA 8.1): 1 RED per 16B instead of 4 scalar REDs.
__device__ __forceinline__ void red_add_v4(float* p, float4 v) {
    asm volatile("red.global.add.v4.f32 [%0], {%1, %2, %3, %4};"
                 :: "l"(p), "f"(v.x), "f"(v.y), "f"(v.z), "f"(v.w) : "memory");
}

// ---------------- zero scratch accumulators ----------------
__global__ __launch_bounds__(256) void k_zero() {
    size_t i = (size_t)blockIdx.x * blockDim.x + threadIdx.x;
    size_t stride = (size_t)gridDim.x * blockDim.x;
    float4 z = make_float4(0.f, 0.f, 0.f, 0.f);
    for (size_t j = i; j < (size_t)MAXE * D / 4; j += stride) {
        ((float4*)g_S1)[j] = z;
        ((float4*)g_S2)[j] = z;
    }
    for (size_t j = i; j < (size_t)MAXN * D / 4; j += stride) {
        ((float4*)g_VF)[j] = z;
        ((float4*)g_VF2)[j] = z;
        ((float4*)g_VF2B)[j] = z;
    }
    for (size_t j = i; j < (size_t)MAXE / 4; j += stride) {
        ((float4*)g_c1)[j] = z;
        ((float4*)g_deg)[j] = z;
    }
}

// ---------------- fused incidence pass 1 ----------------
// S1[d] += invDV[s]*vfeat[s];  VF2[s] += efeat[d];  c1[d] += invDV[s];  deg[d] += 1
__global__ __launch_bounds__(256) void k_scatter1(
        const int* __restrict__ src, const int* __restrict__ dst,
        const float* __restrict__ vfeat, const float* __restrict__ efeat,
        const float* __restrict__ invDV, int nnz) {
    int w = (int)(((size_t)blockIdx.x * blockDim.x + threadIdx.x) >> 5);
    if (w >= nnz) return;
    int lane = threadIdx.x & 31;
    int s = src[w], d = dst[w];
    float iv = invDV[s];
    float4 v = ((const float4*)(vfeat + (size_t)s * D))[lane];
    v.x *= iv; v.y *= iv; v.z *= iv; v.w *= iv;
    red_add_v4(g_S1 + (size_t)d * D + lane * 4, v);
    float4 e = ((const float4*)(efeat + (size_t)d * D))[lane];
    red_add_v4(g_VF2 + (size_t)s * D + lane * 4, e);
    if (lane == 0) {
        atomicAdd(&g_c1[d], iv);
        atomicAdd(&g_deg[d], 1.0f);
    }
}

// ---------------- K=128 GEMM + relu: C[M,128] = relu(X @ W.T) ----------------
// W: [128,128] row-major (row j = output col j).
__global__ __launch_bounds__(256) void k_gemm_relu(const float* __restrict__ X, int M,
                                                   const float* __restrict__ W,
                                                   float* __restrict__ C) {
    __shared__ __align__(16) float Xs[16][132];
    __shared__ __align__(16) float Ws[16][132];
    int tid = threadIdx.x;
    int R0 = blockIdx.x * 128;
    int tr = tid >> 4, tc = tid & 15;
    int lr = tid >> 2;            // 0..63
    int lc = (tid & 3) << 2;      // 0,4,8,12
    float acc[8][8];
#pragma unroll
    for (int i = 0; i < 8; i++)
#pragma unroll
        for (int j = 0; j < 8; j++) acc[i][j] = 0.f;

    for (int kk = 0; kk < 128; kk += 16) {
#pragma unroll
        for (int h = 0; h < 2; h++) {
            int r = lr + h * 64;
            int grow = R0 + r;
            float4 v = make_float4(0.f, 0.f, 0.f, 0.f);
            if (grow < M) v = *(const float4*)(X + (size_t)grow * 128 + kk + lc);
            Xs[lc + 0][r] = v.x; Xs[lc + 1][r] = v.y;
            Xs[lc + 2][r] = v.z; Xs[lc + 3][r] = v.w;
            float4 wv = *(const float4*)(W + (size_t)r * 128 + kk + lc);
            Ws[lc + 0][r] = wv.x; Ws[lc + 1][r] = wv.y;
            Ws[lc + 2][r] = wv.z; Ws[lc + 3][r] = wv.w;
        }
        __syncthreads();
#pragma unroll
        for (int k = 0; k < 16; k++) {
            float a[8], b[8];
            *(float4*)(a + 0) = *(const float4*)&Xs[k][tr * 8];
            *(float4*)(a + 4) = *(const float4*)&Xs[k][tr * 8 + 4];
            *(float4*)(b + 0) = *(const float4*)&Ws[k][tc * 8];
            *(float4*)(b + 4) = *(const float4*)&Ws[k][tc * 8 + 4];
#pragma unroll
            for (int i = 0; i < 8; i++)
#pragma unroll
                for (int j = 0; j < 8; j++) acc[i][j] += a[i] * b[j];
        }
        __syncthreads();
    }

#pragma unroll
    for (int i = 0; i < 8; i++) {
        int row = R0 + tr * 8 + i;
        if (row >= M) continue;
        float out[8];
#pragma unroll
        for (int j = 0; j < 8; j++) out[j] = fmaxf(acc[i][j], 0.f);
        float* cp = C + (size_t)row * 128 + tc * 8;
        *(float4*)(cp + 0) = *(float4*)(out + 0);
        *(float4*)(cp + 4) = *(float4*)(out + 4);
    }
}

// ---------------- K=256 concat GEMM ----------------
// Logical input row: [X1[row] | scale[row]*X2[row]]  (256 wide)
// C[row] = postmul(row) * ( concat_row @ W.T + scale[row]*bias )
// where postmul(row) = post ? post[row] : 1.
// Optional: aux_out[row][:] = aux_in[row][:]  (fused row copy)
// W: [128 outs, 256] row-major.
__global__ __launch_bounds__(256) void k_gemm_cat(const float* __restrict__ X1,
                                                  const float* __restrict__ X2,
                                                  const float* __restrict__ scale,
                                                  const float* __restrict__ post,
                                                  int M,
                                                  const float* __restrict__ W,
                                                  const float* __restrict__ bias,
                                                  float* __restrict__ C,
                                                  const float* __restrict__ aux_in,
                                                  float* __restrict__ aux_out) {
    __shared__ __align__(16) float Xs[16][132];
    __shared__ __align__(16) float Ws[16][132];
    __shared__ float sSc[128];
    int tid = threadIdx.x;
    int R0 = blockIdx.x * 128;
    int tr = tid >> 4, tc = tid & 15;
    int lr = tid >> 2;            // 0..63
    int lc = (tid & 3) << 2;      // 0,4,8,12

    if (tid < 128) {
        int grow = R0 + tid;
        sSc[tid] = (grow < M) ? scale[grow] : 0.f;
    }
    __syncthreads();

    float acc[8][8];
#pragma unroll
    for (int i = 0; i < 8; i++)
#pragma unroll
        for (int j = 0; j < 8; j++) acc[i][j] = 0.f;

    for (int kk = 0; kk < 256; kk += 16) {
        const float* Xsrc = (kk < 128) ? X1 : X2;
        int k2 = (kk < 128) ? kk : (kk - 128);
#pragma unroll
        for (int h = 0; h < 2; h++) {
            int r = lr + h * 64;
            int grow = R0 + r;
            float4 v = make_float4(0.f, 0.f, 0.f, 0.f);
            if (grow < M) {
                v = *(const float4*)(Xsrc + (size_t)grow * 128 + k2 + lc);
                if (kk >= 128) {
                    float sc = sSc[r];
                    v.x *= sc; v.y *= sc; v.z *= sc; v.w *= sc;
                }
            }
            Xs[lc + 0][r] = v.x; Xs[lc + 1][r] = v.y;
            Xs[lc + 2][r] = v.z; Xs[lc + 3][r] = v.w;
            float4 wv = *(const float4*)(W + (size_t)r * 256 + kk + lc);
            Ws[lc + 0][r] = wv.x; Ws[lc + 1][r] = wv.y;
            Ws[lc + 2][r] = wv.z; Ws[lc + 3][r] = wv.w;
        }
        __syncthreads();
#pragma unroll
        for (int k = 0; k < 16; k++) {
            float a[8], b[8];
            *(float4*)(a + 0) = *(const float4*)&Xs[k][tr * 8];
            *(float4*)(a + 4) = *(const float4*)&Xs[k][tr * 8 + 4];
            *(float4*)(b + 0) = *(const float4*)&Ws[k][tc * 8];
            *(float4*)(b + 4) = *(const float4*)&Ws[k][tc * 8 + 4];
#pragma unroll
            for (int i = 0; i < 8; i++)
#pragma unroll
                for (int j = 0; j < 8; j++) acc[i][j] += a[i] * b[j];
        }
        __syncthreads();
    }

    float bv[8];
#pragma unroll
    for (int j = 0; j < 8; j++) bv[j] = bias[tc * 8 + j];
#pragma unroll
    for (int i = 0; i < 8; i++) {
        int row = R0 + tr * 8 + i;
        if (row >= M) continue;
        float sc = sSc[tr * 8 + i];
        float pm = post ? post[row] : 1.f;
        float out[8];
#pragma unroll
        for (int j = 0; j < 8; j++) out[j] = pm * (acc[i][j] + sc * bv[j]);
        float* cp = C + (size_t)row * 128 + tc * 8;
        *(float4*)(cp + 0) = *(float4*)(out + 0);
        *(float4*)(cp + 4) = *(float4*)(out + 4);
        if (aux_out) {
            const float* ai = aux_in + (size_t)row * 128 + tc * 8;
            float* ao = aux_out + (size_t)row * 128 + tc * 8;
            *(float4*)(ao + 0) = *(const float4*)(ai + 0);
            *(float4*)(ao + 4) = *(const float4*)(ai + 4);
        }
    }
}

// ---------------- SpMMs (warp per nnz) ----------------
__global__ __launch_bounds__(256) void k_spmmE(const int* __restrict__ rows,
                                               const int* __restrict__ cols,
                                               const float* __restrict__ vals, int nnz) {
    int w = (int)(((size_t)blockIdx.x * blockDim.x + threadIdx.x) >> 5);
    if (w >= nnz) return;
    int lane = threadIdx.x & 31;
    int r = rows[w], c = cols[w];
    float v = vals[w];
    float4 x = ((const float4*)(g_Apre + (size_t)c * D))[lane];
    x.x *= v; x.y *= v; x.z *= v; x.w *= v;
    red_add_v4(g_EF + (size_t)r * D + lane * 4, x);
}

__global__ __launch_bounds__(256) void k_spmmV(const int* __restrict__ rows,
                                               const int* __restrict__ cols,
                                               const float* __restrict__ vals, int nnz) {
    int w = (int)(((size_t)blockIdx.x * blockDim.x + threadIdx.x) >> 5);
    if (w >= nnz) return;
    int lane = threadIdx.x & 31;
    int r = rows[w], c = cols[w];
    float v = vals[w];
    float4 x = ((const float4*)(g_VF2 + (size_t)c * D))[lane];
    x.x *= v; x.y *= v; x.z *= v; x.w *= v;
    red_add_v4(g_VF2B + (size_t)r * D + lane * 4, x);
}

// ---------------- incidence scatters (warp per nnz) ----------------
// VF[s] += EF[d]
__global__ __launch_bounds__(256) void k_scat_EF_VF(const int* __restrict__ src,
                                                    const int* __restrict__ dst, int nnz) {
    int w = (int)(((size_t)blockIdx.x * blockDim.x + threadIdx.x) >> 5);
    if (w >= nnz) return;
    int lane = threadIdx.x & 31;
    int s = src[w], d = dst[w];
    float4 x = ((const float4*)(g_EF + (size_t)d * D))[lane];
    red_add_v4(g_VF + (size_t)s * D + lane * 4, x);
}

// S2[d] += vout[s]
__global__ __launch_bounds__(256) void k_scat_vout_S2(const int* __restrict__ src,
                                                      const int* __restrict__ dst,
                                                      const float* __restrict__ vout, int nnz) {
    int w = (int)(((size_t)blockIdx.x * blockDim.x + threadIdx.x) >> 5);
    if (w >= nnz) return;
    int lane = threadIdx.x & 31;
    int s = src[w], d = dst[w];
    float4 x = ((const float4*)(vout + (size_t)s * D))[lane];
    red_add_v4(g_S2 + (size_t)d * D + lane * 4, x);
}

// EF2[d] += VF2B[s]
__global__ __launch_bounds__(256) void k_scat_VF2B_EF2(const int* __restrict__ src,
                                                       const int* __restrict__ dst, int nnz) {
    int w = (int)(((size_t)blockIdx.x * blockDim.x + threadIdx.x) >> 5);
    if (w >= nnz) return;
    int lane = threadIdx.x & 31;
    int s = src[w], d = dst[w];
    float4 x = ((const float4*)(g_VF2B + (size_t)s * D))[lane];
    red_add_v4(g_EF2 + (size_t)d * D + lane * 4, x);
}

// ---------------- launch ----------------
extern "C" void kernel_launch(void* const* d_in, const int* in_sizes, int n_in,
                              void* d_out, int out_size) {
    const float* vfeat = (const float*)d_in[0];
    const float* efeat = (const float*)d_in[1];
    const float* invDV = (const float*)d_in[2];
    const float* invDE = (const float*)d_in[3];
    const int*   inc_src = (const int*)d_in[4];
    const int*   inc_dst = (const int*)d_in[5];
    const int*   emr = (const int*)d_in[6];
    const int*   emc = (const int*)d_in[7];
    const float* emv = (const float*)d_in[8];
    const int*   vmr = (const int*)d_in[9];
    const int*   vmc = (const int*)d_in[10];
    const float* vmv = (const float*)d_in[11];
    const float* Wv  = (const float*)d_in[12];
    const float* We  = (const float*)d_in[13];
    const float* p1W = (const float*)d_in[14];
    const float* p1b = (const float*)d_in[15];
    const float* p2W = (const float*)d_in[16];
    const float* p2b = (const float*)d_in[17];

    int N = in_sizes[2];
    int E = in_sizes[3];
    int nnz  = in_sizes[4];
    int nnzE = in_sizes[6];
    int nnzV = in_sizes[9];

    float* vout = (float*)d_out;
    float* eout = vout + (size_t)N * D;

    float *S1, *S2, *VF, *EF2, *Apre, *EF, *c1, *deg;
    cudaGetSymbolAddress((void**)&S1,   g_S1);
    cudaGetSymbolAddress((void**)&S2,   g_S2);
    cudaGetSymbolAddress((void**)&VF,   g_VF);
    cudaGetSymbolAddress((void**)&EF2,  g_EF2);
    cudaGetSymbolAddress((void**)&Apre, g_Apre);
    cudaGetSymbolAddress((void**)&EF,   g_EF);
    cudaGetSymbolAddress((void**)&c1,   g_c1);
    cudaGetSymbolAddress((void**)&deg,  g_deg);

    int gE = divup(E, 128);
    int gN = divup(N, 128);
    int incBlocks  = divup(nnz * 32, 256);
    int emBlocks   = divup(nnzE * 32, 256);
    int vmBlocks   = divup(nnzV * 32, 256);

    // 0. zero accumulators
    k_zero<<<1184, 256>>>();
    // 1. fused incidence pass: S1, c1, deg, VF2
    k_scatter1<<<incBlocks, 256>>>(inc_src, inc_dst, vfeat, efeat, invDV, nnz);
    // 2. Apre = [S1 | c1*efeat]@p1W.T + c1*p1b;  EF = efeat (fused copy)
    k_gemm_cat<<<gE, 256>>>(S1, efeat, c1, nullptr, E, p1W, p1b, Apre, efeat, EF);
    // 3. emat spmm: EF += emat @ Apre   (-> _efeat = efeat + A)
    k_spmmE<<<emBlocks, 256>>>(emr, emc, emv, nnzE);
    // 4. _vfeat: VF[s] += EF[d]
    k_scat_EF_VF<<<incBlocks, 256>>>(inc_src, inc_dst, nnz);
    // 5. vfeat_out = relu(VF @ Wv.T)  -> output part 1
    k_gemm_relu<<<gN, 256>>>(VF, N, Wv, vout);
    // 6. S2[d] += vout[s]
    k_scat_vout_S2<<<incBlocks, 256>>>(inc_src, inc_dst, vout, nnz);
    // 7. EF2 = B = invDE*([S2 | deg*efeat]@p2W.T + deg*p2b)
    k_gemm_cat<<<gE, 256>>>(S2, efeat, deg, invDE, E, p2W, p2b, EF2, nullptr, nullptr);
    // 8. vmat spmm: VF2B += vmat @ VF2
    k_spmmV<<<vmBlocks, 256>>>(vmr, vmc, vmv, nnzV);
    // 9. EF2[d] += VF2B[s]
    k_scat_VF2B_EF2<<<incBlocks, 256>>>(inc_src, inc_dst, nnz);
    // 10. efeat_out = relu(EF2 @ We.T) -> output part 2
    k_gemm_relu<<<gE, 256>>>(EF2, E, We, eout);
}

// round 16
// speedup vs baseline: 1.0636x; 1.0636x over previous
// HNNLayer — R16 (= R11, still unmeasured): batched (NB=4) scatter/SpMM warps; K=256 concat GEMMs
#include <cuda_runtime.h>
#include <cstddef>

#define D 128
#define MAXN 50000
#define MAXE 10000
#define NB 4  // nnz per warp in scatter/spmm kernels

__device__ __align__(16) float g_S1[MAXE * D];
__device__ __align__(16) float g_S2[MAXE * D];
__device__ __align__(16) float g_VF[MAXN * D];
__device__ __align__(16) float g_VF2[MAXN * D];
__device__ __align__(16) float g_VF2B[MAXN * D];
__device__ __align__(16) float g_c1[MAXE];
__device__ __align__(16) float g_deg[MAXE];
__device__ __align__(16) float g_Apre[MAXE * D];
__device__ __align__(16) float g_EF[MAXE * D];
__device__ __align__(16) float g_EF2[MAXE * D];

static inline int divup(int a, int b) { return (a + b - 1) / b; }

__device__ __forceinline__ void red_add_v4(float* p, float4 v) {
    asm volatile("red.global.add.v4.f32 [%0], {%1, %2, %3, %4};"
                 :: "l"(p), "f"(v.x), "f"(v.y), "f"(v.z), "f"(v.w) : "memory");
}

// ---------------- zero scratch accumulators ----------------
__global__ __launch_bounds__(256) void k_zero() {
    size_t i = (size_t)blockIdx.x * blockDim.x + threadIdx.x;
    size_t stride = (size_t)gridDim.x * blockDim.x;
    float4 z = make_float4(0.f, 0.f, 0.f, 0.f);
    for (size_t j = i; j < (size_t)MAXE * D / 4; j += stride) {
        ((float4*)g_S1)[j] = z;
        ((float4*)g_S2)[j] = z;
    }
    for (size_t j = i; j < (size_t)MAXN * D / 4; j += stride) {
        ((float4*)g_VF)[j] = z;
        ((float4*)g_VF2)[j] = z;
        ((float4*)g_VF2B)[j] = z;
    }
    for (size_t j = i; j < (size_t)MAXE / 4; j += stride) {
        ((float4*)g_c1)[j] = z;
        ((float4*)g_deg)[j] = z;
    }
}

// ---------------- fused incidence pass 1 (batched) ----------------
// per nnz: S1[d] += invDV[s]*vfeat[s];  VF2[s] += efeat[d];  c1[d] += invDV[s];  deg[d] += 1
__global__ __launch_bounds__(256) void k_scatter1(
        const int* __restrict__ src, const int* __restrict__ dst,
        const float* __restrict__ vfeat, const float* __restrict__ efeat,
        const float* __restrict__ invDV, int nnz) {
    int w = (int)(((size_t)blockIdx.x * blockDim.x + threadIdx.x) >> 5);
    int lane = threadIdx.x & 31;
    int base = w * NB;
    if (base >= nnz) return;
    int s[NB], d[NB];
    float iv[NB];
    int cnt = min(NB, nnz - base);
#pragma unroll
    for (int j = 0; j < NB; j++) {
        if (j < cnt) { s[j] = src[base + j]; d[j] = dst[base + j]; }
    }
#pragma unroll
    for (int j = 0; j < NB; j++) if (j < cnt) iv[j] = invDV[s[j]];
    float4 v[NB], e[NB];
#pragma unroll
    for (int j = 0; j < NB; j++)
        if (j < cnt) v[j] = ((const float4*)(vfeat + (size_t)s[j] * D))[lane];
#pragma unroll
    for (int j = 0; j < NB; j++)
        if (j < cnt) e[j] = ((const float4*)(efeat + (size_t)d[j] * D))[lane];
#pragma unroll
    for (int j = 0; j < NB; j++) {
        if (j < cnt) {
            float4 t = v[j];
            t.x *= iv[j]; t.y *= iv[j]; t.z *= iv[j]; t.w *= iv[j];
            red_add_v4(g_S1 + (size_t)d[j] * D + lane * 4, t);
            red_add_v4(g_VF2 + (size_t)s[j] * D + lane * 4, e[j]);
        }
    }
    if (lane == 0) {
#pragma unroll
        for (int j = 0; j < NB; j++) {
            if (j < cnt) {
                atomicAdd(&g_c1[d[j]], iv[j]);
                atomicAdd(&g_deg[d[j]], 1.0f);
            }
        }
    }
}

// ---------------- K=128 GEMM + relu: C[M,128] = relu(X @ W.T) ----------------
__global__ __launch_bounds__(256) void k_gemm_relu(const float* __restrict__ X, int M,
                                                   const float* __restrict__ W,
                                                   float* __restrict__ C) {
    __shared__ __align__(16) float Xs[16][132];
    __shared__ __align__(16) float Ws[16][132];
    int tid = threadIdx.x;
    int R0 = blockIdx.x * 128;
    int tr = tid >> 4, tc = tid & 15;
    int lr = tid >> 2;
    int lc = (tid & 3) << 2;
    float acc[8][8];
#pragma unroll
    for (int i = 0; i < 8; i++)
#pragma unroll
        for (int j = 0; j < 8; j++) acc[i][j] = 0.f;

    for (int kk = 0; kk < 128; kk += 16) {
#pragma unroll
        for (int h = 0; h < 2; h++) {
            int r = lr + h * 64;
            int grow = R0 + r;
            float4 v = make_float4(0.f, 0.f, 0.f, 0.f);
            if (grow < M) v = *(const float4*)(X + (size_t)grow * 128 + kk + lc);
            Xs[lc + 0][r] = v.x; Xs[lc + 1][r] = v.y;
            Xs[lc + 2][r] = v.z; Xs[lc + 3][r] = v.w;
            float4 wv = *(const float4*)(W + (size_t)r * 128 + kk + lc);
            Ws[lc + 0][r] = wv.x; Ws[lc + 1][r] = wv.y;
            Ws[lc + 2][r] = wv.z; Ws[lc + 3][r] = wv.w;
        }
        __syncthreads();
#pragma unroll
        for (int k = 0; k < 16; k++) {
            float a[8], b[8];
            *(float4*)(a + 0) = *(const float4*)&Xs[k][tr * 8];
            *(float4*)(a + 4) = *(const float4*)&Xs[k][tr * 8 + 4];
            *(float4*)(b + 0) = *(const float4*)&Ws[k][tc * 8];
            *(float4*)(b + 4) = *(const float4*)&Ws[k][tc * 8 + 4];
#pragma unroll
            for (int i = 0; i < 8; i++)
#pragma unroll
                for (int j = 0; j < 8; j++) acc[i][j] += a[i] * b[j];
        }
        __syncthreads();
    }

#pragma unroll
    for (int i = 0; i < 8; i++) {
        int row = R0 + tr * 8 + i;
        if (row >= M) continue;
        float out[8];
#pragma unroll
        for (int j = 0; j < 8; j++) out[j] = fmaxf(acc[i][j], 0.f);
        float* cp = C + (size_t)row * 128 + tc * 8;
        *(float4*)(cp + 0) = *(float4*)(out + 0);
        *(float4*)(cp + 4) = *(float4*)(out + 4);
    }
}

// ---------------- K=256 concat GEMM ----------------
// C[row] = post(row) * ( [X1[row] | scale[row]*X2[row]] @ W.T + scale[row]*bias )
__global__ __launch_bounds__(256) void k_gemm_cat(const float* __restrict__ X1,
                                                  const float* __restrict__ X2,
                                                  const float* __restrict__ scale,
                                                  const float* __restrict__ post,
                                                  int M,
                                                  const float* __restrict__ W,
                                                  const float* __restrict__ bias,
                                                  float* __restrict__ C,
                                                  const float* __restrict__ aux_in,
                                                  float* __restrict__ aux_out) {
    __shared__ __align__(16) float Xs[16][132];
    __shared__ __align__(16) float Ws[16][132];
    __shared__ float sSc[128];
    int tid = threadIdx.x;
    int R0 = blockIdx.x * 128;
    int tr = tid >> 4, tc = tid & 15;
    int lr = tid >> 2;
    int lc = (tid & 3) << 2;

    if (tid < 128) {
        int grow = R0 + tid;
        sSc[tid] = (grow < M) ? scale[grow] : 0.f;
    }
    __syncthreads();

    float acc[8][8];
#pragma unroll
    for (int i = 0; i < 8; i++)
#pragma unroll
        for (int j = 0; j < 8; j++) acc[i][j] = 0.f;

    for (int kk = 0; kk < 256; kk += 16) {
        const float* Xsrc = (kk < 128) ? X1 : X2;
        int k2 = (kk < 128) ? kk : (kk - 128);
#pragma unroll
        for (int h = 0; h < 2; h++) {
            int r = lr + h * 64;
            int grow = R0 + r;
            float4 v = make_float4(0.f, 0.f, 0.f, 0.f);
            if (grow < M) {
                v = *(const float4*)(Xsrc + (size_t)grow * 128 + k2 + lc);
                if (kk >= 128) {
                    float sc = sSc[r];
                    v.x *= sc; v.y *= sc; v.z *= sc; v.w *= sc;
                }
            }
            Xs[lc + 0][r] = v.x; Xs[lc + 1][r] = v.y;
            Xs[lc + 2][r] = v.z; Xs[lc + 3][r] = v.w;
            float4 wv = *(const float4*)(W + (size_t)r * 256 + kk + lc);
            Ws[lc + 0][r] = wv.x; Ws[lc + 1][r] = wv.y;
            Ws[lc + 2][r] = wv.z; Ws[lc + 3][r] = wv.w;
        }
        __syncthreads();
#pragma unroll
        for (int k = 0; k < 16; k++) {
            float a[8], b[8];
            *(float4*)(a + 0) = *(const float4*)&Xs[k][tr * 8];
            *(float4*)(a + 4) = *(const float4*)&Xs[k][tr * 8 + 4];
            *(float4*)(b + 0) = *(const float4*)&Ws[k][tc * 8];
            *(float4*)(b + 4) = *(const float4*)&Ws[k][tc * 8 + 4];
#pragma unroll
            for (int i = 0; i < 8; i++)
#pragma unroll
                for (int j = 0; j < 8; j++) acc[i][j] += a[i] * b[j];
        }
        __syncthreads();
    }

    float bv[8];
#pragma unroll
    for (int j = 0; j < 8; j++) bv[j] = bias[tc * 8 + j];
#pragma unroll
    for (int i = 0; i < 8; i++) {
        int row = R0 + tr * 8 + i;
        if (row >= M) continue;
        float sc = sSc[tr * 8 + i];
        float pm = post ? post[row] : 1.f;
        float out[8];
#pragma unroll
        for (int j = 0; j < 8; j++) out[j] = pm * (acc[i][j] + sc * bv[j]);
        float* cp = C + (size_t)row * 128 + tc * 8;
        *(float4*)(cp + 0) = *(float4*)(out + 0);
        *(float4*)(cp + 4) = *(float4*)(out + 4);
        if (aux_out) {
            const float* ai = aux_in + (size_t)row * 128 + tc * 8;
            float* ao = aux_out + (size_t)row * 128 + tc * 8;
            *(float4*)(ao + 0) = *(const float4*)(ai + 0);
            *(float4*)(ao + 4) = *(const float4*)(ai + 4);
        }
    }
}

// ---------------- batched SpMM: OUT[r] += val * IN[c]  (warp handles NB nnz) ----------------
__global__ __launch_bounds__(256) void k_spmm(const int* __restrict__ rows,
                                              const int* __restrict__ cols,
                                              const float* __restrict__ vals,
                                              const float* __restrict__ IN,
                                              float* __restrict__ OUT, int nnz) {
    int w = (int)(((size_t)blockIdx.x * blockDim.x + threadIdx.x) >> 5);
    int lane = threadIdx.x & 31;
    int base = w * NB;
    if (base >= nnz) return;
    int cnt = min(NB, nnz - base);
    int r[NB], c[NB];
    float v[NB];
#pragma unroll
    for (int j = 0; j < NB; j++)
        if (j < cnt) { r[j] = rows[base + j]; c[j] = cols[base + j]; v[j] = vals[base + j]; }
    float4 x[NB];
#pragma unroll
    for (int j = 0; j < NB; j++)
        if (j < cnt) x[j] = ((const float4*)(IN + (size_t)c[j] * D))[lane];
#pragma unroll
    for (int j = 0; j < NB; j++) {
        if (j < cnt) {
            float4 t = x[j];
            t.x *= v[j]; t.y *= v[j]; t.z *= v[j]; t.w *= v[j];
            red_add_v4(OUT + (size_t)r[j] * D + lane * 4, t);
        }
    }
}

// ---------------- batched incidence scatter: OUT[oidx[i]] += IN[iidx[i]] ----------------
__global__ __launch_bounds__(256) void k_scat(const int* __restrict__ iidx,
                                              const int* __restrict__ oidx,
                                              const float* __restrict__ IN,
                                              float* __restrict__ OUT, int nnz) {
    int w = (int)(((size_t)blockIdx.x * blockDim.x + threadIdx.x) >> 5);
    int lane = threadIdx.x & 31;
    int base = w * NB;
    if (base >= nnz) return;
    int cnt = min(NB, nnz - base);
    int si[NB], so[NB];
#pragma unroll
    for (int j = 0; j < NB; j++)
        if (j < cnt) { si[j] = iidx[base + j]; so[j] = oidx[base + j]; }
    float4 x[NB];
#pragma unroll
    for (int j = 0; j < NB; j++)
        if (j < cnt) x[j] = ((const float4*)(IN + (size_t)si[j] * D))[lane];
#pragma unroll
    for (int j = 0; j < NB; j++)
        if (j < cnt) red_add_v4(OUT + (size_t)so[j] * D + lane * 4, x[j]);
}

// ---------------- launch ----------------
extern "C" void kernel_launch(void* const* d_in, const int* in_sizes, int n_in,
                              void* d_out, int out_size) {
    const float* vfeat = (const float*)d_in[0];
    const float* efeat = (const float*)d_in[1];
    const float* invDV = (const float*)d_in[2];
    const float* invDE = (const float*)d_in[3];
    const int*   inc_src = (const int*)d_in[4];
    const int*   inc_dst = (const int*)d_in[5];
    const int*   emr = (const int*)d_in[6];
    const int*   emc = (const int*)d_in[7];
    const float* emv = (const float*)d_in[8];
    const int*   vmr = (const int*)d_in[9];
    const int*   vmc = (const int*)d_in[10];
    const float* vmv = (const float*)d_in[11];
    const float* Wv  = (const float*)d_in[12];
    const float* We  = (const float*)d_in[13];
    const float* p1W = (const float*)d_in[14];
    const float* p1b = (const float*)d_in[15];
    const float* p2W = (const float*)d_in[16];
    const float* p2b = (const float*)d_in[17];

    int N = in_sizes[2];
    int E = in_sizes[3];
    int nnz  = in_sizes[4];
    int nnzE = in_sizes[6];
    int nnzV = in_sizes[9];

    float* vout = (float*)d_out;
    float* eout = vout + (size_t)N * D;

    float *S1, *S2, *VF, *VF2, *VF2B, *EF2, *Apre, *EF, *c1, *deg;
    cudaGetSymbolAddress((void**)&S1,   g_S1);
    cudaGetSymbolAddress((void**)&S2,   g_S2);
    cudaGetSymbolAddress((void**)&VF,   g_VF);
    cudaGetSymbolAddress((void**)&VF2,  g_VF2);
    cudaGetSymbolAddress((void**)&VF2B, g_VF2B);
    cudaGetSymbolAddress((void**)&EF2,  g_EF2);
    cudaGetSymbolAddress((void**)&Apre, g_Apre);
    cudaGetSymbolAddress((void**)&EF,   g_EF);
    cudaGetSymbolAddress((void**)&c1,   g_c1);
    cudaGetSymbolAddress((void**)&deg,  g_deg);

    int gE = divup(E, 128);
    int gN = divup(N, 128);
    int incBlocks = divup(divup(nnz,  NB) * 32, 256);
    int emBlocks  = divup(divup(nnzE, NB) * 32, 256);
    int vmBlocks  = divup(divup(nnzV, NB) * 32, 256);

    // 0. zero accumulators
    k_zero<<<1184, 256>>>();
    // 1. fused incidence pass: S1, c1, deg, VF2
    k_scatter1<<<incBlocks, 256>>>(inc_src, inc_dst, vfeat, efeat, invDV, nnz);
    // 2. Apre = [S1 | c1*efeat]@p1W.T + c1*p1b;  EF = efeat (fused copy)
    k_gemm_cat<<<gE, 256>>>(S1, efeat, c1, nullptr, E, p1W, p1b, Apre, efeat, EF);
    // 3. emat spmm: EF += emat @ Apre   (-> _efeat = efeat + A)
    k_spmm<<<emBlocks, 256>>>(emr, emc, emv, Apre, EF, nnzE);
    // 4. _vfeat: VF[s] += EF[d]
    k_scat<<<incBlocks, 256>>>(inc_dst, inc_src, EF, VF, nnz);
    // 5. vfeat_out = relu(VF @ Wv.T)  -> output part 1
    k_gemm_relu<<<gN, 256>>>(VF, N, Wv, vout);
    // 6. S2[d] += vout[s]
    k_scat<<<incBlocks, 256>>>(inc_src, inc_dst, vout, S2, nnz);
    // 7. EF2 = B = invDE*([S2 | deg*efeat]@p2W.T + deg*p2b)
    k_gemm_cat<<<gE, 256>>>(S2, efeat, deg, invDE, E, p2W, p2b, EF2, nullptr, nullptr);
    // 8. vmat spmm: VF2B += vmat @ VF2
    k_spmm<<<vmBlocks, 256>>>(vmr, vmc, vmv, VF2, VF2B, nnzV);
    // 9. EF2[d] += VF2B[s]
    k_scat<<<incBlocks, 256>>>(inc_src, inc_dst, VF2B, EF2, nnz);
    // 10. efeat_out = relu(EF2 @ We.T) -> output part 2
    k_gemm_relu<<<gE, 256>>>(EF2, E, We, eout);
}